// round 2
// baseline (speedup 1.0000x reference)
#include <cuda_runtime.h>
#include <cuda_fp16.h>

#define SEQ 2048
#define DMODEL 1024
#define NH 16
#define DK 64
#define NB 2
#define ROWS (NB*SEQ)

// scratch (device globals: allocation-free)
__device__ float g_q[ROWS*DMODEL];
__device__ float g_k[ROWS*DK];
__device__ float g_v[ROWS*DK];
__device__ float g_x[ROWS*DMODEL];

__device__ __forceinline__ unsigned f2tf(float f){
    unsigned r; asm("cvt.rna.tf32.f32 %0, %1;" : "=r"(r) : "f"(f)); return r;
}

__device__ __forceinline__ void mma_tf32(float* c, const unsigned* a, unsigned b0, unsigned b1){
    asm volatile("mma.sync.aligned.m16n8k8.row.col.f32.tf32.tf32.f32 "
        "{%0,%1,%2,%3},{%4,%5,%6,%7},{%8,%9},{%0,%1,%2,%3};"
        : "+f"(c[0]),"+f"(c[1]),"+f"(c[2]),"+f"(c[3])
        : "r"(a[0]),"r"(a[1]),"r"(a[2]),"r"(a[3]),"r"(b0),"r"(b1));
}

__device__ __forceinline__ void mma_f16(float* c, unsigned a0,unsigned a1,unsigned a2,unsigned a3,
                                        unsigned b0, unsigned b1){
    asm volatile("mma.sync.aligned.m16n8k16.row.col.f32.f16.f16.f32 "
        "{%0,%1,%2,%3},{%4,%5,%6,%7},{%8,%9},{%0,%1,%2,%3};"
        : "+f"(c[0]),"+f"(c[1]),"+f"(c[2]),"+f"(c[3])
        : "r"(a0),"r"(a1),"r"(a2),"r"(a3),"r"(b0),"r"(b1));
}

// ---------------------------------------------------------------------------
// Generic tf32 GEMM: C[M,N] = A[M,K] @ W[K,N] + bias. Row-major everything.
// BM=128, BN=64, BK=32. 256 threads = 8 warps in 4(m) x 2(n) grid,
// each warp computes 32x32 via 2 m16-tiles x 4 n8-tiles.
// ---------------------------------------------------------------------------
__global__ __launch_bounds__(256) void gemm_tf32_kernel(
    const float* __restrict__ A, const float* __restrict__ W,
    const float* __restrict__ bias, float* __restrict__ C,
    int M, int N, int K)
{
    __shared__ __align__(16) unsigned sA[128*36];  // [m][k] padded
    __shared__ __align__(16) unsigned sW[32*72];   // [k][n] padded

    const int tid  = threadIdx.x;
    const int warp = tid >> 5, lane = tid & 31;
    const int g = lane >> 2, t = lane & 3;
    const int wm = warp >> 1, wn = warp & 1;
    const int m0 = blockIdx.y * 128, n0 = blockIdx.x * 64;

    float acc[2][4][4];
#pragma unroll
    for (int a=0;a<2;a++)
#pragma unroll
        for (int b=0;b<4;b++)
#pragma unroll
            for (int c=0;c<4;c++) acc[a][b][c]=0.f;

    for (int k0 = 0; k0 < K; k0 += 32){
        __syncthreads();
        // stage A tile 128x32
        {
            const int r = tid >> 3, f = tid & 7;
#pragma unroll
            for (int p = 0; p < 4; p++){
                float4 v = *(const float4*)&A[(size_t)(m0 + r + p*32)*K + k0 + f*4];
                unsigned* d = &sA[(r + p*32)*36 + f*4];
                d[0]=f2tf(v.x); d[1]=f2tf(v.y); d[2]=f2tf(v.z); d[3]=f2tf(v.w);
            }
        }
        // stage W tile 32x64
        {
            const int r = tid >> 4, f = tid & 15;
#pragma unroll
            for (int p = 0; p < 2; p++){
                float4 v = *(const float4*)&W[(size_t)(k0 + r + p*16)*N + n0 + f*4];
                unsigned* d = &sW[(r + p*16)*72 + f*4];
                d[0]=f2tf(v.x); d[1]=f2tf(v.y); d[2]=f2tf(v.z); d[3]=f2tf(v.w);
            }
        }
        __syncthreads();
#pragma unroll
        for (int kb = 0; kb < 4; kb++){
            unsigned af[2][4], bf[4][2];
#pragma unroll
            for (int mt = 0; mt < 2; mt++){
                int row = wm*32 + mt*16;
                af[mt][0] = sA[(row+g  )*36 + kb*8 + t];
                af[mt][1] = sA[(row+g+8)*36 + kb*8 + t];
                af[mt][2] = sA[(row+g  )*36 + kb*8 + t + 4];
                af[mt][3] = sA[(row+g+8)*36 + kb*8 + t + 4];
            }
#pragma unroll
            for (int nt = 0; nt < 4; nt++){
                int col = wn*32 + nt*8 + g;
                bf[nt][0] = sW[(kb*8 + t    )*72 + col];
                bf[nt][1] = sW[(kb*8 + t + 4)*72 + col];
            }
#pragma unroll
            for (int mt = 0; mt < 2; mt++)
#pragma unroll
                for (int nt = 0; nt < 4; nt++)
                    mma_tf32(acc[mt][nt], af[mt], bf[nt][0], bf[nt][1]);
        }
    }
    // epilogue
#pragma unroll
    for (int mt = 0; mt < 2; mt++){
        int row = m0 + wm*32 + mt*16;
#pragma unroll
        for (int nt = 0; nt < 4; nt++){
            int col = n0 + wn*32 + nt*8 + 2*t;
            float b0 = bias[col], b1 = bias[col+1];
            float2 v0 = make_float2(acc[mt][nt][0] + b0, acc[mt][nt][1] + b1);
            float2 v1 = make_float2(acc[mt][nt][2] + b0, acc[mt][nt][3] + b1);
            *(float2*)&C[(size_t)(row + g    )*N + col] = v0;
            *(float2*)&C[(size_t)(row + g + 8)*N + col] = v1;
        }
    }
}

// ---------------------------------------------------------------------------
// Flash attention over flattened rows (b, s, h): M = B*S*H = 65536, N = 2048,
// D = 64. 128-row CTA tile = 8 s-values x 16 heads -> one warp = one s value
// (16 head-rows). QK^T in tf32 mma, P*V in fp16 mma. Mask shared across heads.
// ---------------------------------------------------------------------------
__global__ __launch_bounds__(256) void flash_kernel(
    const float* __restrict__ qp, const float* __restrict__ kp,
    const float* __restrict__ vp, const int* __restrict__ mask,
    float* __restrict__ xo)
{
    __shared__ __align__(16) unsigned smem[128*68];   // 34816 B pool
    unsigned* sK   = smem;                                    // [64][68] tf32
    __half*   sV   = reinterpret_cast<__half*>(smem + 64*68); // [64][72] half (transposed: [d][seq])
    float*    sMsk = reinterpret_cast<float*>(smem + 64*68 + 64*36); // [8][64]

    const int tid  = threadIdx.x;
    const int warp = tid >> 5, lane = tid & 31;
    const int g = lane >> 2, t = lane & 3;

    const int m0 = blockIdx.x * 128;
    const int b  = m0 >> 15;              // / (S*H)
    const int s0 = (m0 & 32767) >> 4;     // / H
    const int sbase = b * SEQ;
    const float scale = 0.125f;           // 1/sqrt(64)

    // ---- stage Q (scaled, tf32) into smem pool: [128][68] ----
    {
        const int r = tid >> 1, fb = (tid & 1) * 8;
        const int s = s0 + (r >> 4), h = r & 15;
        const float* qrow = &qp[(size_t)(sbase + s)*DMODEL + h*64];
#pragma unroll
        for (int i = 0; i < 8; i++){
            float4 v = *(const float4*)&qrow[(fb + i)*4];
            unsigned* d = &smem[r*68 + (fb + i)*4];
            d[0]=f2tf(v.x*scale); d[1]=f2tf(v.y*scale);
            d[2]=f2tf(v.z*scale); d[3]=f2tf(v.w*scale);
        }
    }
    __syncthreads();
    // Q A-fragments for 8 k8-steps, held in registers for the whole kernel
    unsigned qa[8][4];
#pragma unroll
    for (int kt = 0; kt < 8; kt++){
        int row = warp*16;
        qa[kt][0] = smem[(row+g  )*68 + kt*8 + t];
        qa[kt][1] = smem[(row+g+8)*68 + kt*8 + t];
        qa[kt][2] = smem[(row+g  )*68 + kt*8 + t + 4];
        qa[kt][3] = smem[(row+g+8)*68 + kt*8 + t + 4];
    }
    __syncthreads();   // pool is now free for K/V/mask

    float o[8][4];
#pragma unroll
    for (int i=0;i<8;i++){ o[i][0]=0.f;o[i][1]=0.f;o[i][2]=0.f;o[i][3]=0.f; }
    float mrow0 = -1e30f, mrow1 = -1e30f, l0 = 0.f, l1 = 0.f;

    for (int nk = 0; nk < SEQ; nk += 64){
        // ---- stage K [64][68] tf32 ----
        {
            const int r = tid >> 2, cq = (tid & 3);
            const float* krow = &kp[(size_t)(sbase + nk + r)*64];
#pragma unroll
            for (int i = 0; i < 4; i++){
                float4 v = *(const float4*)&krow[cq*16 + i*4];
                unsigned* d = &sK[r*68 + cq*16 + i*4];
                d[0]=f2tf(v.x); d[1]=f2tf(v.y); d[2]=f2tf(v.z); d[3]=f2tf(v.w);
            }
        }
        // ---- stage V transposed [d][seq] fp16 ----
        {
            const int r = tid >> 2, cq = (tid & 3);
            const float* vrow = &vp[(size_t)(sbase + nk + r)*64];
#pragma unroll
            for (int i = 0; i < 4; i++){
                float4 v = *(const float4*)&vrow[cq*16 + i*4];
                int c = cq*16 + i*4;
                sV[(c+0)*72 + r] = __float2half(v.x);
                sV[(c+1)*72 + r] = __float2half(v.y);
                sV[(c+2)*72 + r] = __float2half(v.z);
                sV[(c+3)*72 + r] = __float2half(v.w);
            }
        }
        // ---- stage mask bias [8][64] ----
        {
            const int ss = tid >> 5, j0 = (tid & 31)*2;
            int2 mv = *(const int2*)&mask[((size_t)sbase + s0 + ss)*SEQ + nk + j0];
            sMsk[ss*64 + j0    ] = mv.x ? 0.f : -1e9f;
            sMsk[ss*64 + j0 + 1] = mv.y ? 0.f : -1e9f;
        }
        __syncthreads();

        // ---- S = Q K^T (+mask) ----
        float sf[8][4];
#pragma unroll
        for (int nt = 0; nt < 8; nt++){
            sf[nt][0]=0.f; sf[nt][1]=0.f; sf[nt][2]=0.f; sf[nt][3]=0.f;
#pragma unroll
            for (int kt = 0; kt < 8; kt++){
                unsigned b0 = sK[(nt*8+g)*68 + kt*8 + t];
                unsigned b1 = sK[(nt*8+g)*68 + kt*8 + t + 4];
                mma_tf32(sf[nt], qa[kt], b0, b1);
            }
            float mb0 = sMsk[warp*64 + nt*8 + 2*t];
            float mb1 = sMsk[warp*64 + nt*8 + 2*t + 1];
            sf[nt][0] += mb0; sf[nt][1] += mb1;
            sf[nt][2] += mb0; sf[nt][3] += mb1;
        }

        // ---- online softmax ----
        float mx0 = -1e30f, mx1 = -1e30f;
#pragma unroll
        for (int nt = 0; nt < 8; nt++){
            mx0 = fmaxf(mx0, fmaxf(sf[nt][0], sf[nt][1]));
            mx1 = fmaxf(mx1, fmaxf(sf[nt][2], sf[nt][3]));
        }
        mx0 = fmaxf(mx0, __shfl_xor_sync(0xffffffffu, mx0, 1));
        mx0 = fmaxf(mx0, __shfl_xor_sync(0xffffffffu, mx0, 2));
        mx1 = fmaxf(mx1, __shfl_xor_sync(0xffffffffu, mx1, 1));
        mx1 = fmaxf(mx1, __shfl_xor_sync(0xffffffffu, mx1, 2));

        float mn0 = fmaxf(mrow0, mx0), mn1 = fmaxf(mrow1, mx1);
        float sc0 = __expf(mrow0 - mn0), sc1 = __expf(mrow1 - mn1);
        mrow0 = mn0; mrow1 = mn1;

        float sum0 = 0.f, sum1 = 0.f;
        unsigned pl[8], ph[8];
#pragma unroll
        for (int nt = 0; nt < 8; nt++){
            float p0 = __expf(sf[nt][0] - mn0);
            float p1 = __expf(sf[nt][1] - mn0);
            float p2 = __expf(sf[nt][2] - mn1);
            float p3 = __expf(sf[nt][3] - mn1);
            sum0 += p0 + p1; sum1 += p2 + p3;
            __half2 h0 = __floats2half2_rn(p0, p1);
            __half2 h1 = __floats2half2_rn(p2, p3);
            pl[nt] = *(unsigned*)&h0;
            ph[nt] = *(unsigned*)&h1;
        }
        sum0 += __shfl_xor_sync(0xffffffffu, sum0, 1);
        sum0 += __shfl_xor_sync(0xffffffffu, sum0, 2);
        sum1 += __shfl_xor_sync(0xffffffffu, sum1, 1);
        sum1 += __shfl_xor_sync(0xffffffffu, sum1, 2);
        l0 = l0*sc0 + sum0; l1 = l1*sc1 + sum1;

#pragma unroll
        for (int nv = 0; nv < 8; nv++){
            o[nv][0] *= sc0; o[nv][1] *= sc0;
            o[nv][2] *= sc1; o[nv][3] *= sc1;
        }

        // ---- O += P V  (fp16 m16n8k16) ----
        const unsigned* sV32 = (const unsigned*)sV;  // row stride 36 words
#pragma unroll
        for (int kt2 = 0; kt2 < 4; kt2++){
            unsigned a0 = pl[2*kt2], a1 = ph[2*kt2];
            unsigned a2 = pl[2*kt2+1], a3 = ph[2*kt2+1];
#pragma unroll
            for (int nv = 0; nv < 8; nv++){
                unsigned b0 = sV32[(nv*8+g)*36 + kt2*8 + t];
                unsigned b1 = sV32[(nv*8+g)*36 + kt2*8 + 4 + t];
                mma_f16(o[nv], a0, a1, a2, a3, b0, b1);
            }
        }
        __syncthreads();
    }

    // ---- normalize + write: row (warp s-value, head g / g+8) ----
    float inv0 = 1.f / l0, inv1 = 1.f / l1;
    float* orow = &xo[(size_t)(sbase + s0 + warp)*DMODEL];
#pragma unroll
    for (int nv = 0; nv < 8; nv++){
        int col = nv*8 + 2*t;
        *(float2*)&orow[g*64 + col] =
            make_float2(o[nv][0]*inv0, o[nv][1]*inv0);
        *(float2*)&orow[(g+8)*64 + col] =
            make_float2(o[nv][2]*inv1, o[nv][3]*inv1);
    }
}

// ---------------------------------------------------------------------------
extern "C" void kernel_launch(void* const* d_in, const int* in_sizes, int n_in,
                              void* d_out, int out_size)
{
    const float* query = (const float*)d_in[0];
    const float* key   = (const float*)d_in[1];
    const float* value = (const float*)d_in[2];
    const int*   mask  = (const int*)  d_in[3];
    const float* Wq = (const float*)d_in[4];
    const float* bq = (const float*)d_in[5];
    const float* Wk = (const float*)d_in[6];
    const float* bk = (const float*)d_in[7];
    const float* Wv = (const float*)d_in[8];
    const float* bv = (const float*)d_in[9];
    const float* Wo = (const float*)d_in[10];
    const float* bo = (const float*)d_in[11];
    float* out = (float*)d_out;

    float *gq, *gk, *gv, *gx;
    cudaGetSymbolAddress((void**)&gq, g_q);
    cudaGetSymbolAddress((void**)&gk, g_k);
    cudaGetSymbolAddress((void**)&gv, g_v);
    cudaGetSymbolAddress((void**)&gx, g_x);

    // projections
    gemm_tf32_kernel<<<dim3(DMODEL/64, ROWS/128), 256>>>(query, Wq, bq, gq, ROWS, DMODEL, DMODEL);
    gemm_tf32_kernel<<<dim3(1,         ROWS/128), 256>>>(key,   Wk, bk, gk, ROWS, DK,     DMODEL);
    gemm_tf32_kernel<<<dim3(1,         ROWS/128), 256>>>(value, Wv, bv, gv, ROWS, DK,     DMODEL);

    // fused multi-head attention (MQA flattened to one flash problem)
    flash_kernel<<<(NB*SEQ*NH)/128, 256>>>(gq, gk, gv, mask, gx);

    // output projection
    gemm_tf32_kernel<<<dim3(DMODEL/64, ROWS/128), 256>>>(gx, Wo, bo, out, ROWS, DMODEL, DMODEL);
}

// round 3
// speedup vs baseline: 2.3380x; 2.3380x over previous
#include <cuda_runtime.h>
#include <cuda_fp16.h>

#define SEQ 2048
#define DMODEL 1024
#define NH 16
#define DK 64
#define NB 2
#define ROWS (NB*SEQ)

// ---------------- scratch (device globals: allocation-free) ----------------
__device__ __half h_query[ROWS*DMODEL];
__device__ __half h_key  [ROWS*DMODEL];
__device__ __half h_value[ROWS*DMODEL];
__device__ __half h_Wq[DMODEL*DMODEL];
__device__ __half h_Wo[DMODEL*DMODEL];
__device__ __half h_Wk[DMODEL*DK];
__device__ __half h_Wv[DMODEL*DK];
__device__ __half h_q [ROWS*DMODEL];
__device__ __half h_kv[ROWS*2*DK];        // packed [4096][128]: cols 0-63 K, 64-127 V
__device__ __half h_x [ROWS*DMODEL];

// ---------------- ptx helpers ----------------
__device__ __forceinline__ unsigned su32(const void* p){
    return (unsigned)__cvta_generic_to_shared(p);
}
__device__ __forceinline__ void cp16(unsigned s, const void* g){
    asm volatile("cp.async.ca.shared.global [%0], [%1], 16;" :: "r"(s), "l"(g));
}
__device__ __forceinline__ void cp_commit(){ asm volatile("cp.async.commit_group;"); }
template<int N> __device__ __forceinline__ void cp_wait(){
    asm volatile("cp.async.wait_group %0;" :: "n"(N));
}
__device__ __forceinline__ void ldm4(unsigned& r0,unsigned& r1,unsigned& r2,unsigned& r3,unsigned a){
    asm volatile("ldmatrix.sync.aligned.m8n8.x4.shared.b16 {%0,%1,%2,%3}, [%4];"
        : "=r"(r0),"=r"(r1),"=r"(r2),"=r"(r3) : "r"(a));
}
__device__ __forceinline__ void ldm4t(unsigned& r0,unsigned& r1,unsigned& r2,unsigned& r3,unsigned a){
    asm volatile("ldmatrix.sync.aligned.m8n8.x4.trans.shared.b16 {%0,%1,%2,%3}, [%4];"
        : "=r"(r0),"=r"(r1),"=r"(r2),"=r"(r3) : "r"(a));
}
__device__ __forceinline__ void mma_f16(float* c, unsigned a0,unsigned a1,unsigned a2,unsigned a3,
                                        unsigned b0, unsigned b1){
    asm volatile("mma.sync.aligned.m16n8k16.row.col.f32.f16.f16.f32 "
        "{%0,%1,%2,%3},{%4,%5,%6,%7},{%8,%9},{%0,%1,%2,%3};"
        : "+f"(c[0]),"+f"(c[1]),"+f"(c[2]),"+f"(c[3])
        : "r"(a0),"r"(a1),"r"(a2),"r"(a3),"r"(b0),"r"(b1));
}
__device__ __forceinline__ void st2(__half* p, float x, float y){
    *(__half2*)p = __floats2half2_rn(x, y);
}
__device__ __forceinline__ void st2(float* p, float x, float y){
    *(float2*)p = make_float2(x, y);
}

// ---------------- fp32 -> fp16 convert ----------------
__global__ void f2h_kernel(const float* __restrict__ src, __half* __restrict__ dst,
                           int n, float scale){
    int i = (blockIdx.x*blockDim.x + threadIdx.x)*4;
    if (i < n){
        float4 v = *(const float4*)&src[i];
        *(__half2*)&dst[i]   = __floats2half2_rn(v.x*scale, v.y*scale);
        *(__half2*)&dst[i+2] = __floats2half2_rn(v.z*scale, v.w*scale);
    }
}

// ---------------------------------------------------------------------------
// fp16 GEMM: C[M,N] = A[M,K] @ W[K,N] + bias*bscale.
// Output written with row stride CST (>= N) at column offset coff  -> lets the
// K-proj and V-proj write interleaved halves of the packed h_kv buffer.
// BM=128, BN template, BK=32. 256 threads, 8 warps (4m x 2n).
// cp.async double-buffered, ldmatrix fragments, fp16 m16n8k16 mma, f32 accum.
// ---------------------------------------------------------------------------
template<int BN, typename OUT>
__global__ __launch_bounds__(256) void gemm_h(
    const __half* __restrict__ A, const __half* __restrict__ W,
    const float* __restrict__ bias, OUT* __restrict__ C,
    int M, int N, int K, float bscale, int CST, int coff)
{
    constexpr int AST = 40;            // A smem row stride (halfs): 80B, bank-coprime
    constexpr int WST = BN + 8;        // W smem row stride
    constexpr int WN  = BN/2;          // warp n extent
    constexpr int NG  = WN/16;         // n16 groups per warp
    __shared__ __half sA[2][128*AST];
    __shared__ __half sW[2][32*WST];

    const int tid = threadIdx.x, warp = tid>>5, lane = tid&31;
    const int wm = warp & 3, wn = warp >> 2;
    const int m0 = blockIdx.y*128, n0 = blockIdx.x*BN;
    const int g = lane>>2, t = lane&3;

    float acc[2][NG*2][4];
#pragma unroll
    for (int a=0;a<2;a++)
#pragma unroll
        for (int b=0;b<NG*2;b++)
#pragma unroll
            for (int c=0;c<4;c++) acc[a][b][c]=0.f;

    auto stage = [&](int kt, int buf){
        int c = tid*2;
#pragma unroll
        for (int i=0;i<2;i++,c++){
            int r = c>>2, cc = c&3;
            cp16(su32(&sA[buf][r*AST + cc*8]),
                 &A[(size_t)(m0+r)*K + kt*32 + cc*8]);
        }
        constexpr int WC = BN/8;
#pragma unroll
        for (int c2=tid; c2 < 32*WC; c2 += 256){
            int r = c2/WC, cc = c2%WC;
            cp16(su32(&sW[buf][r*WST + cc*8]),
                 &W[(size_t)(kt*32+r)*N + n0 + cc*8]);
        }
    };

    const int KT = K/32;
    stage(0,0); cp_commit();

    for (int kt = 0; kt < KT; kt++){
        if (kt+1 < KT){ stage(kt+1, (kt+1)&1); cp_commit(); cp_wait<1>(); }
        else          { cp_wait<0>(); }
        __syncthreads();
        const __half* cA = sA[kt&1];
        const __half* cW = sW[kt&1];
#pragma unroll
        for (int ks=0; ks<2; ks++){
            unsigned a[2][4];
#pragma unroll
            for (int mt=0; mt<2; mt++){
                int row = wm*32 + mt*16 + (lane&7) + ((lane>>3)&1)*8;
                int col = ks*16 + (lane>>4)*8;
                ldm4(a[mt][0],a[mt][1],a[mt][2],a[mt][3], su32(&cA[row*AST+col]));
            }
            unsigned bfr[NG][4];
#pragma unroll
            for (int ng=0; ng<NG; ng++){
                int row = ks*16 + (lane&15);
                int col = wn*WN + ng*16 + (lane>>4)*8;
                ldm4t(bfr[ng][0],bfr[ng][1],bfr[ng][2],bfr[ng][3], su32(&cW[row*WST+col]));
            }
#pragma unroll
            for (int mt=0; mt<2; mt++)
#pragma unroll
                for (int ng=0; ng<NG; ng++){
                    mma_f16(acc[mt][ng*2],   a[mt][0],a[mt][1],a[mt][2],a[mt][3],
                            bfr[ng][0],bfr[ng][1]);
                    mma_f16(acc[mt][ng*2+1], a[mt][0],a[mt][1],a[mt][2],a[mt][3],
                            bfr[ng][2],bfr[ng][3]);
                }
        }
        __syncthreads();
    }

#pragma unroll
    for (int mt=0; mt<2; mt++){
        int row = m0 + wm*32 + mt*16;
#pragma unroll
        for (int nt=0; nt<NG*2; nt++){
            int col = n0 + wn*WN + nt*8 + 2*t;
            float b0 = bias[col]*bscale, b1 = bias[col+1]*bscale;
            st2(&C[(size_t)(row+g  )*CST + coff + col], acc[mt][nt][0]+b0, acc[mt][nt][1]+b1);
            st2(&C[(size_t)(row+g+8)*CST + coff + col], acc[mt][nt][2]+b0, acc[mt][nt][3]+b1);
        }
    }
}

// ---------------------------------------------------------------------------
// fp16 flash attention, MQA flattened: rows (b,s,h), M=65536, N=2048, D=64.
// CTA = 128 rows = 8 s x 16 heads; warp = one s (16 head-rows).
// Q pre-scaled by 1/8 (folded into Wq/bq). K|V packed in h_kv (row stride 128).
// cp.async double-buffered K/V/mask tiles of 64 keys, ldmatrix fragments.
// ---------------------------------------------------------------------------
__global__ __launch_bounds__(256) void flash_h(
    const __half* __restrict__ qp, const __half* __restrict__ kvp,
    const int* __restrict__ mask, __half* __restrict__ xo)
{
    constexpr int ST = 72;    // smem row stride halfs (144B, bank-coprime)
    __shared__ __half sK[2][64*ST];
    __shared__ __half sV[2][64*ST];
    __shared__ int    sM[2][8*64];
    __half* sQ = &sK[0][0];   // 128*72 halfs == both sK buffers, reused in prologue

    const int tid = threadIdx.x, warp = tid>>5, lane = tid&31;
    const int g = lane>>2, t = lane&3;
    const int m0 = blockIdx.x*128;
    const int b  = m0 >> 15;
    const int s0 = (m0 & 32767) >> 4;
    const int sbase = b*SEQ;

    // ---- stage Q [128][64] via cp.async, extract A-fragments ----
    {
        int c = tid*4;
#pragma unroll
        for (int i=0;i<4;i++,c++){
            int r = c>>3, cc = c&7;
            cp16(su32(&sQ[r*ST + cc*8]),
                 &qp[(size_t)(sbase + s0 + (r>>4))*DMODEL + (r&15)*64 + cc*8]);
        }
        cp_commit(); cp_wait<0>();
        __syncthreads();
    }
    unsigned qa[4][4];
#pragma unroll
    for (int ks=0; ks<4; ks++){
        int row = warp*16 + (lane&7) + ((lane>>3)&1)*8;
        int col = ks*16 + (lane>>4)*8;
        ldm4(qa[ks][0],qa[ks][1],qa[ks][2],qa[ks][3], su32(&sQ[row*ST+col]));
    }
    __syncthreads();    // sQ region free -> K buffers

    float o[8][4];
#pragma unroll
    for (int i=0;i<8;i++){ o[i][0]=0.f;o[i][1]=0.f;o[i][2]=0.f;o[i][3]=0.f; }
    float mrow0=-1e30f, mrow1=-1e30f, l0=0.f, l1=0.f;

    auto stage = [&](int nk, int buf){
        int c = tid*2;
#pragma unroll
        for (int i=0;i<2;i++,c++){
            int r = c>>3, cc = c&7;
            const __half* kvrow = &kvp[(size_t)(sbase + nk + r)*(2*DK)];
            cp16(su32(&sK[buf][r*ST + cc*8]), kvrow + cc*8);
            cp16(su32(&sV[buf][r*ST + cc*8]), kvrow + DK + cc*8);
        }
        if (tid < 128){
            int r = tid>>4, cc = tid&15;
            cp16(su32(&sM[buf][r*64 + cc*4]),
                 &mask[((size_t)b*SEQ + s0 + r)*SEQ + nk + cc*4]);
        }
    };

    stage(0,0); cp_commit();

    for (int it = 0; it < SEQ/64; it++){
        if (it+1 < SEQ/64){ stage((it+1)*64, (it+1)&1); cp_commit(); cp_wait<1>(); }
        else              { cp_wait<0>(); }
        __syncthreads();
        const __half* cK = sK[it&1];
        const __half* cV = sV[it&1];
        const int*    cM = sM[it&1];

        // ---- S = Q K^T + mask ----
        float sf[8][4];
#pragma unroll
        for (int jt=0; jt<8; jt++){
            unsigned kb[8];
            {
                int row = jt*8 + (lane&7);
                int col = (lane>>3)*8;
                ldm4(kb[0],kb[1],kb[2],kb[3], su32(&cK[row*ST + col]));
                ldm4(kb[4],kb[5],kb[6],kb[7], su32(&cK[row*ST + 32 + col]));
            }
            sf[jt][0]=0.f; sf[jt][1]=0.f; sf[jt][2]=0.f; sf[jt][3]=0.f;
            mma_f16(sf[jt], qa[0][0],qa[0][1],qa[0][2],qa[0][3], kb[0],kb[1]);
            mma_f16(sf[jt], qa[1][0],qa[1][1],qa[1][2],qa[1][3], kb[2],kb[3]);
            mma_f16(sf[jt], qa[2][0],qa[2][1],qa[2][2],qa[2][3], kb[4],kb[5]);
            mma_f16(sf[jt], qa[3][0],qa[3][1],qa[3][2],qa[3][3], kb[6],kb[7]);
            float mb0 = cM[warp*64 + jt*8 + 2*t    ] ? 0.f : -1e9f;
            float mb1 = cM[warp*64 + jt*8 + 2*t + 1] ? 0.f : -1e9f;
            sf[jt][0]+=mb0; sf[jt][1]+=mb1; sf[jt][2]+=mb0; sf[jt][3]+=mb1;
        }

        // ---- online softmax ----
        float mx0=-1e30f, mx1=-1e30f;
#pragma unroll
        for (int jt=0; jt<8; jt++){
            mx0 = fmaxf(mx0, fmaxf(sf[jt][0], sf[jt][1]));
            mx1 = fmaxf(mx1, fmaxf(sf[jt][2], sf[jt][3]));
        }
        mx0 = fmaxf(mx0, __shfl_xor_sync(0xffffffffu, mx0, 1));
        mx0 = fmaxf(mx0, __shfl_xor_sync(0xffffffffu, mx0, 2));
        mx1 = fmaxf(mx1, __shfl_xor_sync(0xffffffffu, mx1, 1));
        mx1 = fmaxf(mx1, __shfl_xor_sync(0xffffffffu, mx1, 2));

        float mn0 = fmaxf(mrow0, mx0), mn1 = fmaxf(mrow1, mx1);
        float sc0 = __expf(mrow0 - mn0), sc1 = __expf(mrow1 - mn1);
        mrow0 = mn0; mrow1 = mn1;

        float sum0=0.f, sum1=0.f;
        unsigned pl[8], ph[8];
#pragma unroll
        for (int jt=0; jt<8; jt++){
            float p0 = __expf(sf[jt][0]-mn0);
            float p1 = __expf(sf[jt][1]-mn0);
            float p2 = __expf(sf[jt][2]-mn1);
            float p3 = __expf(sf[jt][3]-mn1);
            sum0 += p0+p1; sum1 += p2+p3;
            __half2 h0 = __floats2half2_rn(p0,p1);
            __half2 h1 = __floats2half2_rn(p2,p3);
            pl[jt] = *(unsigned*)&h0;
            ph[jt] = *(unsigned*)&h1;
        }
        sum0 += __shfl_xor_sync(0xffffffffu, sum0, 1);
        sum0 += __shfl_xor_sync(0xffffffffu, sum0, 2);
        sum1 += __shfl_xor_sync(0xffffffffu, sum1, 1);
        sum1 += __shfl_xor_sync(0xffffffffu, sum1, 2);
        l0 = l0*sc0 + sum0; l1 = l1*sc1 + sum1;

#pragma unroll
        for (int nv=0; nv<8; nv++){
            o[nv][0]*=sc0; o[nv][1]*=sc0; o[nv][2]*=sc1; o[nv][3]*=sc1;
        }

        // ---- O += P V ----
#pragma unroll
        for (int kt2=0; kt2<4; kt2++){
            unsigned a0 = pl[2*kt2],   a1 = ph[2*kt2];
            unsigned a2 = pl[2*kt2+1], a3 = ph[2*kt2+1];
#pragma unroll
            for (int dp=0; dp<4; dp++){
                unsigned r0,r1,r2,r3;
                int row = kt2*16 + (lane&15);
                int col = dp*16 + (lane>>4)*8;
                ldm4t(r0,r1,r2,r3, su32(&cV[row*ST + col]));
                mma_f16(o[dp*2],   a0,a1,a2,a3, r0,r1);
                mma_f16(o[dp*2+1], a0,a1,a2,a3, r2,r3);
            }
        }
        __syncthreads();
    }

    // ---- normalize + write fp16 ----
    float inv0 = 1.f/l0, inv1 = 1.f/l1;
    __half* orow = &xo[(size_t)(sbase + s0 + warp)*DMODEL];
#pragma unroll
    for (int nt=0; nt<8; nt++){
        int col = nt*8 + 2*t;
        st2(&orow[g*64 + col],     o[nt][0]*inv0, o[nt][1]*inv0);
        st2(&orow[(g+8)*64 + col], o[nt][2]*inv1, o[nt][3]*inv1);
    }
}

// ---------------------------------------------------------------------------
extern "C" void kernel_launch(void* const* d_in, const int* in_sizes, int n_in,
                              void* d_out, int out_size)
{
    const float* query = (const float*)d_in[0];
    const float* key   = (const float*)d_in[1];
    const float* value = (const float*)d_in[2];
    const int*   mask  = (const int*)  d_in[3];
    const float* Wq = (const float*)d_in[4];
    const float* bq = (const float*)d_in[5];
    const float* Wk = (const float*)d_in[6];
    const float* bk = (const float*)d_in[7];
    const float* Wv = (const float*)d_in[8];
    const float* bv = (const float*)d_in[9];
    const float* Wo = (const float*)d_in[10];
    const float* bo = (const float*)d_in[11];
    float* out = (float*)d_out;

    __half *gquery,*gkey,*gvalue,*gWq,*gWo,*gWk,*gWv,*gq,*gkv,*gx;
    cudaGetSymbolAddress((void**)&gquery, h_query);
    cudaGetSymbolAddress((void**)&gkey,   h_key);
    cudaGetSymbolAddress((void**)&gvalue, h_value);
    cudaGetSymbolAddress((void**)&gWq,    h_Wq);
    cudaGetSymbolAddress((void**)&gWo,    h_Wo);
    cudaGetSymbolAddress((void**)&gWk,    h_Wk);
    cudaGetSymbolAddress((void**)&gWv,    h_Wv);
    cudaGetSymbolAddress((void**)&gq,     h_q);
    cudaGetSymbolAddress((void**)&gkv,    h_kv);
    cudaGetSymbolAddress((void**)&gx,     h_x);

    const int NACT = ROWS*DMODEL;     // 4M
    const int NW   = DMODEL*DMODEL;   // 1M
    const int NWK  = DMODEL*DK;       // 64K

    // converts (Wq folds the 1/sqrt(dk)=0.125 attention scale; bq via bscale)
    f2h_kernel<<<NACT/1024, 256>>>(query, gquery, NACT, 1.f);
    f2h_kernel<<<NACT/1024, 256>>>(key,   gkey,   NACT, 1.f);
    f2h_kernel<<<NACT/1024, 256>>>(value, gvalue, NACT, 1.f);
    f2h_kernel<<<NW/1024,   256>>>(Wq, gWq, NW, 0.125f);
    f2h_kernel<<<NW/1024,   256>>>(Wo, gWo, NW, 1.f);
    f2h_kernel<<<NWK/1024,  256>>>(Wk, gWk, NWK, 1.f);
    f2h_kernel<<<NWK/1024,  256>>>(Wv, gWv, NWK, 1.f);

    // projections (K and V write interleaved halves of packed h_kv, stride 128)
    gemm_h<128,__half><<<dim3(DMODEL/128, ROWS/128), 256>>>(
        gquery, gWq, bq, gq, ROWS, DMODEL, DMODEL, 0.125f, DMODEL, 0);
    gemm_h<64,__half><<<dim3(1, ROWS/128), 256>>>(
        gkey,   gWk, bk, gkv, ROWS, DK, DMODEL, 1.f, 2*DK, 0);
    gemm_h<64,__half><<<dim3(1, ROWS/128), 256>>>(
        gvalue, gWv, bv, gkv, ROWS, DK, DMODEL, 1.f, 2*DK, DK);

    // fused MQA flash attention
    flash_h<<<(NB*SEQ*NH)/128, 256>>>(gq, gkv, mask, gx);

    // output projection (fp32 out)
    gemm_h<128,float><<<dim3(DMODEL/128, ROWS/128), 256>>>(
        gx, gWo, bo, out, ROWS, DMODEL, DMODEL, 1.f, DMODEL, 0);
}

// round 4
// speedup vs baseline: 2.6517x; 1.1342x over previous
#include <cuda_runtime.h>
#include <cuda_fp16.h>

#define SEQ 2048
#define DMODEL 1024
#define NH 16
#define DK 64
#define NB 2
#define ROWS (NB*SEQ)

// 0.125 * log2(e): folds both the 1/sqrt(dk) scale and the exp->exp2 change
#define QSCALE 0.18033688f

// ---------------- scratch (device globals: allocation-free) ----------------
__device__ __half h_query[ROWS*DMODEL];
__device__ __half h_key  [ROWS*DMODEL];
__device__ __half h_value[ROWS*DMODEL];
__device__ __half h_Wq[DMODEL*DMODEL];
__device__ __half h_Wo[DMODEL*DMODEL];
__device__ __half h_Wk[DMODEL*DK];
__device__ __half h_Wv[DMODEL*DK];
__device__ __half h_q [ROWS*DMODEL];
__device__ __half h_kv[ROWS*2*DK];        // packed [4096][128]: cols 0-63 K, 64-127 V
__device__ __half h_x [ROWS*DMODEL];

// ---------------- ptx helpers ----------------
__device__ __forceinline__ unsigned su32(const void* p){
    return (unsigned)__cvta_generic_to_shared(p);
}
__device__ __forceinline__ void cp16(unsigned s, const void* g){
    asm volatile("cp.async.ca.shared.global [%0], [%1], 16;" :: "r"(s), "l"(g));
}
__device__ __forceinline__ void cp_commit(){ asm volatile("cp.async.commit_group;"); }
template<int N> __device__ __forceinline__ void cp_wait(){
    asm volatile("cp.async.wait_group %0;" :: "n"(N));
}
__device__ __forceinline__ void ldm4(unsigned& r0,unsigned& r1,unsigned& r2,unsigned& r3,unsigned a){
    asm volatile("ldmatrix.sync.aligned.m8n8.x4.shared.b16 {%0,%1,%2,%3}, [%4];"
        : "=r"(r0),"=r"(r1),"=r"(r2),"=r"(r3) : "r"(a));
}
__device__ __forceinline__ void ldm4t(unsigned& r0,unsigned& r1,unsigned& r2,unsigned& r3,unsigned a){
    asm volatile("ldmatrix.sync.aligned.m8n8.x4.trans.shared.b16 {%0,%1,%2,%3}, [%4];"
        : "=r"(r0),"=r"(r1),"=r"(r2),"=r"(r3) : "r"(a));
}
__device__ __forceinline__ void mma_f16(float* c, unsigned a0,unsigned a1,unsigned a2,unsigned a3,
                                        unsigned b0, unsigned b1){
    asm volatile("mma.sync.aligned.m16n8k16.row.col.f32.f16.f16.f32 "
        "{%0,%1,%2,%3},{%4,%5,%6,%7},{%8,%9},{%0,%1,%2,%3};"
        : "+f"(c[0]),"+f"(c[1]),"+f"(c[2]),"+f"(c[3])
        : "r"(a0),"r"(a1),"r"(a2),"r"(a3),"r"(b0),"r"(b1));
}
__device__ __forceinline__ float ex2(float x){
    float r; asm("ex2.approx.f32 %0, %1;" : "=f"(r) : "f"(x)); return r;
}
__device__ __forceinline__ void st2(__half* p, float x, float y){
    *(__half2*)p = __floats2half2_rn(x, y);
}
__device__ __forceinline__ void st2(float* p, float x, float y){
    *(float2*)p = make_float2(x, y);
}

// ---------------- fp32 -> fp16 converts (merged launches, 8 elem/thread) ----
__global__ void f2h_acts(const float* __restrict__ q, const float* __restrict__ k,
                         const float* __restrict__ v){
    const float* s; __half* d;
    if      (blockIdx.z == 0){ s = q; d = h_query; }
    else if (blockIdx.z == 1){ s = k; d = h_key;   }
    else                     { s = v; d = h_value; }
    int i = (blockIdx.x*blockDim.x + threadIdx.x)*8;
    float4 a = *(const float4*)&s[i];
    float4 b2 = *(const float4*)&s[i+4];
    *(__half2*)&d[i]   = __floats2half2_rn(a.x, a.y);
    *(__half2*)&d[i+2] = __floats2half2_rn(a.z, a.w);
    *(__half2*)&d[i+4] = __floats2half2_rn(b2.x, b2.y);
    *(__half2*)&d[i+6] = __floats2half2_rn(b2.z, b2.w);
}
__global__ void f2h_wts(const float* __restrict__ Wq, const float* __restrict__ Wo,
                        const float* __restrict__ Wk, const float* __restrict__ Wv){
    const float* s; __half* d; int n; float sc;
    if      (blockIdx.z == 0){ s=Wq; d=h_Wq; n=DMODEL*DMODEL; sc=QSCALE; }
    else if (blockIdx.z == 1){ s=Wo; d=h_Wo; n=DMODEL*DMODEL; sc=1.f; }
    else if (blockIdx.z == 2){ s=Wk; d=h_Wk; n=DMODEL*DK;     sc=1.f; }
    else                     { s=Wv; d=h_Wv; n=DMODEL*DK;     sc=1.f; }
    int i = (blockIdx.x*blockDim.x + threadIdx.x)*8;
    if (i < n){
        float4 a = *(const float4*)&s[i];
        float4 b2 = *(const float4*)&s[i+4];
        *(__half2*)&d[i]   = __floats2half2_rn(a.x*sc, a.y*sc);
        *(__half2*)&d[i+2] = __floats2half2_rn(a.z*sc, a.w*sc);
        *(__half2*)&d[i+4] = __floats2half2_rn(b2.x*sc, b2.y*sc);
        *(__half2*)&d[i+6] = __floats2half2_rn(b2.z*sc, b2.w*sc);
    }
}

// ---------------------------------------------------------------------------
// fp16 GEMM core: C[M,N] = A[M,K] @ W[K,N] + bias*bscale.
// Output row stride CST (>= N) at column offset coff.
// BM=128, BN template, BK=32. 256 threads, 8 warps (4m x 2n).
// cp.async double-buffered, ldmatrix fragments, fp16 m16n8k16 mma, f32 accum.
// ---------------------------------------------------------------------------
template<int BN, typename OUT>
__device__ __forceinline__ void gemm_core(
    const __half* __restrict__ A, const __half* __restrict__ W,
    const float* __restrict__ bias, OUT* __restrict__ C,
    int M, int N, int K, float bscale, int CST, int coff,
    __half* sAbase, __half* sWbase)
{
    constexpr int AST = 40;            // A smem row stride (halfs)
    constexpr int WST = BN + 8;        // W smem row stride
    constexpr int WN  = BN/2;          // warp n extent
    constexpr int NG  = WN/16;         // n16 groups per warp

    const int tid = threadIdx.x, warp = tid>>5, lane = tid&31;
    const int wm = warp & 3, wn = warp >> 2;
    const int m0 = blockIdx.y*128, n0 = blockIdx.x*BN;
    const int g = lane>>2, t = lane&3;

    float acc[2][NG*2][4];
#pragma unroll
    for (int a=0;a<2;a++)
#pragma unroll
        for (int b=0;b<NG*2;b++)
#pragma unroll
            for (int c=0;c<4;c++) acc[a][b][c]=0.f;

    auto stage = [&](int kt, int buf){
        __half* sA = sAbase + buf*(128*AST);
        __half* sW = sWbase + buf*(32*WST);
        int c = tid*2;
#pragma unroll
        for (int i=0;i<2;i++,c++){
            int r = c>>2, cc = c&3;
            cp16(su32(&sA[r*AST + cc*8]),
                 &A[(size_t)(m0+r)*K + kt*32 + cc*8]);
        }
        constexpr int WC = BN/8;
#pragma unroll
        for (int c2=tid; c2 < 32*WC; c2 += 256){
            int r = c2/WC, cc = c2%WC;
            cp16(su32(&sW[r*WST + cc*8]),
                 &W[(size_t)(kt*32+r)*N + n0 + cc*8]);
        }
    };

    const int KT = K/32;
    stage(0,0); cp_commit();

    for (int kt = 0; kt < KT; kt++){
        if (kt+1 < KT){ stage(kt+1, (kt+1)&1); cp_commit(); cp_wait<1>(); }
        else          { cp_wait<0>(); }
        __syncthreads();
        const __half* cA = sAbase + (kt&1)*(128*AST);
        const __half* cW = sWbase + (kt&1)*(32*WST);
#pragma unroll
        for (int ks=0; ks<2; ks++){
            unsigned a[2][4];
#pragma unroll
            for (int mt=0; mt<2; mt++){
                int row = wm*32 + mt*16 + (lane&7) + ((lane>>3)&1)*8;
                int col = ks*16 + (lane>>4)*8;
                ldm4(a[mt][0],a[mt][1],a[mt][2],a[mt][3], su32(&cA[row*AST+col]));
            }
            unsigned bfr[NG][4];
#pragma unroll
            for (int ng=0; ng<NG; ng++){
                int row = ks*16 + (lane&15);
                int col = wn*WN + ng*16 + (lane>>4)*8;
                ldm4t(bfr[ng][0],bfr[ng][1],bfr[ng][2],bfr[ng][3], su32(&cW[row*WST+col]));
            }
#pragma unroll
            for (int mt=0; mt<2; mt++)
#pragma unroll
                for (int ng=0; ng<NG; ng++){
                    mma_f16(acc[mt][ng*2],   a[mt][0],a[mt][1],a[mt][2],a[mt][3],
                            bfr[ng][0],bfr[ng][1]);
                    mma_f16(acc[mt][ng*2+1], a[mt][0],a[mt][1],a[mt][2],a[mt][3],
                            bfr[ng][2],bfr[ng][3]);
                }
        }
        __syncthreads();
    }

#pragma unroll
    for (int mt=0; mt<2; mt++){
        int row = m0 + wm*32 + mt*16;
#pragma unroll
        for (int nt=0; nt<NG*2; nt++){
            int col = n0 + wn*WN + nt*8 + 2*t;
            float b0 = bias[col]*bscale, b1 = bias[col+1]*bscale;
            st2(&C[(size_t)(row+g  )*CST + coff + col], acc[mt][nt][0]+b0, acc[mt][nt][1]+b1);
            st2(&C[(size_t)(row+g+8)*CST + coff + col], acc[mt][nt][2]+b0, acc[mt][nt][3]+b1);
        }
    }
}

// BN=128 instantiation (Q-proj / O-proj)
template<typename OUT>
__global__ __launch_bounds__(256,2) void gemm128_k(
    const __half* __restrict__ A, const __half* __restrict__ W,
    const float* __restrict__ bias, OUT* __restrict__ C,
    int M, int N, int K, float bscale)
{
    __shared__ __half sA[2*128*40];
    __shared__ __half sW[2*32*136];
    gemm_core<128,OUT>(A, W, bias, C, M, N, K, bscale, N, 0, sA, sW);
}

// BN=64, K-proj and V-proj merged via blockIdx.z into packed h_kv
__global__ __launch_bounds__(256,2) void gemm_kv_k(
    const __half* __restrict__ Ak, const __half* __restrict__ Av,
    const __half* __restrict__ Wk, const __half* __restrict__ Wv,
    const float* __restrict__ bk, const float* __restrict__ bv,
    __half* __restrict__ C)
{
    __shared__ __half sA[2*128*40];
    __shared__ __half sW[2*32*72];
    const int z = blockIdx.z;
    gemm_core<64,__half>(z ? Av : Ak, z ? Wv : Wk, z ? bv : bk, C,
                         ROWS, DK, DMODEL, 1.f, 2*DK, z*DK, sA, sW);
}

// ---------------------------------------------------------------------------
// fp16 flash attention, MQA flattened: rows (b,s,h), M=65536, N=2048, D=64.
// CTA = 128 rows = 8 s x 16 heads; warp = one s (16 head-rows).
// Q pre-scaled by 0.125*log2(e) (folded into Wq/bq) -> softmax via ex2.
// K|V packed in h_kv (row stride 128). cp.async double-buffered 64-key tiles.
// ---------------------------------------------------------------------------
__global__ __launch_bounds__(256,2) void flash_h(
    const __half* __restrict__ qp, const __half* __restrict__ kvp,
    const int* __restrict__ mask, __half* __restrict__ xo)
{
    constexpr int ST = 72;    // smem row stride halfs (144B, bank-coprime)
    __shared__ __half sK[2][64*ST];
    __shared__ __half sV[2][64*ST];
    __shared__ int    sM[2][8*64];
    __half* sQ = &sK[0][0];   // 128*72 halfs == both sK buffers, reused in prologue

    const int tid = threadIdx.x, warp = tid>>5, lane = tid&31;
    const int g = lane>>2, t = lane&3;
    const int m0 = blockIdx.x*128;
    const int b  = m0 >> 15;
    const int s0 = (m0 & 32767) >> 4;
    const int sbase = b*SEQ;

    // ---- stage Q [128][64] via cp.async, extract A-fragments ----
    {
        int c = tid*4;
#pragma unroll
        for (int i=0;i<4;i++,c++){
            int r = c>>3, cc = c&7;
            cp16(su32(&sQ[r*ST + cc*8]),
                 &qp[(size_t)(sbase + s0 + (r>>4))*DMODEL + (r&15)*64 + cc*8]);
        }
        cp_commit(); cp_wait<0>();
        __syncthreads();
    }
    unsigned qa[4][4];
#pragma unroll
    for (int ks=0; ks<4; ks++){
        int row = warp*16 + (lane&7) + ((lane>>3)&1)*8;
        int col = ks*16 + (lane>>4)*8;
        ldm4(qa[ks][0],qa[ks][1],qa[ks][2],qa[ks][3], su32(&sQ[row*ST+col]));
    }
    __syncthreads();    // sQ region free -> K buffers

    float o[8][4];
#pragma unroll
    for (int i=0;i<8;i++){ o[i][0]=0.f;o[i][1]=0.f;o[i][2]=0.f;o[i][3]=0.f; }
    float mrow0=-1e30f, mrow1=-1e30f, l0=0.f, l1=0.f;

    auto stage = [&](int nk, int buf){
        int c = tid*2;
#pragma unroll
        for (int i=0;i<2;i++,c++){
            int r = c>>3, cc = c&7;
            const __half* kvrow = &kvp[(size_t)(sbase + nk + r)*(2*DK)];
            cp16(su32(&sK[buf][r*ST + cc*8]), kvrow + cc*8);
            cp16(su32(&sV[buf][r*ST + cc*8]), kvrow + DK + cc*8);
        }
        if (tid < 128){
            int r = tid>>4, cc = tid&15;
            cp16(su32(&sM[buf][r*64 + cc*4]),
                 &mask[((size_t)b*SEQ + s0 + r)*SEQ + nk + cc*4]);
        }
    };

    stage(0,0); cp_commit();

    for (int it = 0; it < SEQ/64; it++){
        if (it+1 < SEQ/64){ stage((it+1)*64, (it+1)&1); cp_commit(); cp_wait<1>(); }
        else              { cp_wait<0>(); }
        __syncthreads();
        const __half* cK = sK[it&1];
        const __half* cV = sV[it&1];
        const int*    cM = sM[it&1];

        // ---- S = Q K^T + mask (log2 domain) ----
        float sf[8][4];
#pragma unroll
        for (int jt=0; jt<8; jt++){
            unsigned kb[8];
            {
                int row = jt*8 + (lane&7);
                int col = (lane>>3)*8;
                ldm4(kb[0],kb[1],kb[2],kb[3], su32(&cK[row*ST + col]));
                ldm4(kb[4],kb[5],kb[6],kb[7], su32(&cK[row*ST + 32 + col]));
            }
            sf[jt][0]=0.f; sf[jt][1]=0.f; sf[jt][2]=0.f; sf[jt][3]=0.f;
            mma_f16(sf[jt], qa[0][0],qa[0][1],qa[0][2],qa[0][3], kb[0],kb[1]);
            mma_f16(sf[jt], qa[1][0],qa[1][1],qa[1][2],qa[1][3], kb[2],kb[3]);
            mma_f16(sf[jt], qa[2][0],qa[2][1],qa[2][2],qa[2][3], kb[4],kb[5]);
            mma_f16(sf[jt], qa[3][0],qa[3][1],qa[3][2],qa[3][3], kb[6],kb[7]);
            float mb0 = cM[warp*64 + jt*8 + 2*t    ] ? 0.f : -1e9f;
            float mb1 = cM[warp*64 + jt*8 + 2*t + 1] ? 0.f : -1e9f;
            sf[jt][0]+=mb0; sf[jt][1]+=mb1; sf[jt][2]+=mb0; sf[jt][3]+=mb1;
        }

        // ---- online softmax (base 2) ----
        float mx0=-1e30f, mx1=-1e30f;
#pragma unroll
        for (int jt=0; jt<8; jt++){
            mx0 = fmaxf(mx0, fmaxf(sf[jt][0], sf[jt][1]));
            mx1 = fmaxf(mx1, fmaxf(sf[jt][2], sf[jt][3]));
        }
        mx0 = fmaxf(mx0, __shfl_xor_sync(0xffffffffu, mx0, 1));
        mx0 = fmaxf(mx0, __shfl_xor_sync(0xffffffffu, mx0, 2));
        mx1 = fmaxf(mx1, __shfl_xor_sync(0xffffffffu, mx1, 1));
        mx1 = fmaxf(mx1, __shfl_xor_sync(0xffffffffu, mx1, 2));

        float mn0 = fmaxf(mrow0, mx0), mn1 = fmaxf(mrow1, mx1);
        float sc0 = ex2(mrow0 - mn0), sc1 = ex2(mrow1 - mn1);
        mrow0 = mn0; mrow1 = mn1;

        float sum0=0.f, sum1=0.f;
        unsigned pl[8], ph[8];
#pragma unroll
        for (int jt=0; jt<8; jt++){
            float p0 = ex2(sf[jt][0]-mn0);
            float p1 = ex2(sf[jt][1]-mn0);
            float p2 = ex2(sf[jt][2]-mn1);
            float p3 = ex2(sf[jt][3]-mn1);
            sum0 += p0+p1; sum1 += p2+p3;
            __half2 h0 = __floats2half2_rn(p0,p1);
            __half2 h1 = __floats2half2_rn(p2,p3);
            pl[jt] = *(unsigned*)&h0;
            ph[jt] = *(unsigned*)&h1;
        }
        sum0 += __shfl_xor_sync(0xffffffffu, sum0, 1);
        sum0 += __shfl_xor_sync(0xffffffffu, sum0, 2);
        sum1 += __shfl_xor_sync(0xffffffffu, sum1, 1);
        sum1 += __shfl_xor_sync(0xffffffffu, sum1, 2);
        l0 = l0*sc0 + sum0; l1 = l1*sc1 + sum1;

#pragma unroll
        for (int nv=0; nv<8; nv++){
            o[nv][0]*=sc0; o[nv][1]*=sc0; o[nv][2]*=sc1; o[nv][3]*=sc1;
        }

        // ---- O += P V ----
#pragma unroll
        for (int kt2=0; kt2<4; kt2++){
            unsigned a0 = pl[2*kt2],   a1 = ph[2*kt2];
            unsigned a2 = pl[2*kt2+1], a3 = ph[2*kt2+1];
#pragma unroll
            for (int dp=0; dp<4; dp++){
                unsigned r0,r1,r2,r3;
                int row = kt2*16 + (lane&15);
                int col = dp*16 + (lane>>4)*8;
                ldm4t(r0,r1,r2,r3, su32(&cV[row*ST + col]));
                mma_f16(o[dp*2],   a0,a1,a2,a3, r0,r1);
                mma_f16(o[dp*2+1], a0,a1,a2,a3, r2,r3);
            }
        }
        __syncthreads();
    }

    // ---- normalize + write fp16 ----
    float inv0 = 1.f/l0, inv1 = 1.f/l1;
    __half* orow = &xo[(size_t)(sbase + s0 + warp)*DMODEL];
#pragma unroll
    for (int nt=0; nt<8; nt++){
        int col = nt*8 + 2*t;
        st2(&orow[g*64 + col],     o[nt][0]*inv0, o[nt][1]*inv0);
        st2(&orow[(g+8)*64 + col], o[nt][2]*inv1, o[nt][3]*inv1);
    }
}

// ---------------------------------------------------------------------------
extern "C" void kernel_launch(void* const* d_in, const int* in_sizes, int n_in,
                              void* d_out, int out_size)
{
    const float* query = (const float*)d_in[0];
    const float* key   = (const float*)d_in[1];
    const float* value = (const float*)d_in[2];
    const int*   mask  = (const int*)  d_in[3];
    const float* Wq = (const float*)d_in[4];
    const float* bq = (const float*)d_in[5];
    const float* Wk = (const float*)d_in[6];
    const float* bk = (const float*)d_in[7];
    const float* Wv = (const float*)d_in[8];
    const float* bv = (const float*)d_in[9];
    const float* Wo = (const float*)d_in[10];
    const float* bo = (const float*)d_in[11];
    float* out = (float*)d_out;

    __half *gquery,*gkey,*gvalue,*gWq,*gWo,*gWk,*gWv,*gq,*gkv,*gx;
    cudaGetSymbolAddress((void**)&gquery, h_query);
    cudaGetSymbolAddress((void**)&gkey,   h_key);
    cudaGetSymbolAddress((void**)&gvalue, h_value);
    cudaGetSymbolAddress((void**)&gWq,    h_Wq);
    cudaGetSymbolAddress((void**)&gWo,    h_Wo);
    cudaGetSymbolAddress((void**)&gWk,    h_Wk);
    cudaGetSymbolAddress((void**)&gWv,    h_Wv);
    cudaGetSymbolAddress((void**)&gq,     h_q);
    cudaGetSymbolAddress((void**)&gkv,    h_kv);
    cudaGetSymbolAddress((void**)&gx,     h_x);

    const int NACT = ROWS*DMODEL;     // 4M
    const int NW   = DMODEL*DMODEL;   // 1M

    // converts: one launch for activations, one for all weights
    f2h_acts<<<dim3(NACT/2048, 1, 3), 256>>>(query, key, value);
    f2h_wts <<<dim3(NW/2048,   1, 4), 256>>>(Wq, Wo, Wk, Wv);

    // projections (Q; K & V merged, writing interleaved halves of h_kv)
    gemm128_k<__half><<<dim3(DMODEL/128, ROWS/128), 256>>>(
        gquery, gWq, bq, gq, ROWS, DMODEL, DMODEL, QSCALE);
    gemm_kv_k<<<dim3(1, ROWS/128, 2), 256>>>(
        gkey, gvalue, gWk, gWv, bk, bv, gkv);

    // fused MQA flash attention
    flash_h<<<(NB*SEQ*NH)/128, 256>>>(gq, gkv, mask, gx);

    // output projection (fp32 out)
    gemm128_k<float><<<dim3(DMODEL/128, ROWS/128), 256>>>(
        gx, gWo, bo, out, ROWS, DMODEL, DMODEL, 1.f);
}

// round 6
// speedup vs baseline: 2.7655x; 1.0429x over previous
#include <cuda_runtime.h>
#include <cuda_fp16.h>
#include <cstdint>

#define SEQ 2048
#define DMODEL 1024
#define NH 16
#define DK 64
#define NB 2
#define ROWS (NB*SEQ)

// 0.125 * log2(e): folds the 1/sqrt(dk) scale and the exp->exp2 change
#define QSCALE 0.18033688f

// ---------------- scratch (device globals: allocation-free) ----------------
__device__ __half h_query[ROWS*DMODEL];
__device__ __half h_key  [ROWS*DMODEL];
__device__ __half h_value[ROWS*DMODEL];
__device__ __half h_Wq[DMODEL*DMODEL];
__device__ __half h_Wo[DMODEL*DMODEL];
__device__ __half h_Wk[DMODEL*DK];
__device__ __half h_Wv[DMODEL*DK];
__device__ __half h_q [ROWS*DMODEL];
__device__ __half h_kv[ROWS*2*DK];        // packed [4096][128]: cols 0-63 K, 64-127 V
__device__ __half h_x [ROWS*DMODEL];

// ---------------- ptx helpers ----------------
__device__ __forceinline__ unsigned su32(const void* p){
    return (unsigned)__cvta_generic_to_shared(p);
}
__device__ __forceinline__ void cp16(unsigned s, const void* g){
    asm volatile("cp.async.ca.shared.global [%0], [%1], 16;" :: "r"(s), "l"(g));
}
__device__ __forceinline__ void cp_commit(){ asm volatile("cp.async.commit_group;"); }
template<int N> __device__ __forceinline__ void cp_wait(){
    asm volatile("cp.async.wait_group %0;" :: "n"(N));
}
__device__ __forceinline__ void ldm4(unsigned& r0,unsigned& r1,unsigned& r2,unsigned& r3,unsigned a){
    asm volatile("ldmatrix.sync.aligned.m8n8.x4.shared.b16 {%0,%1,%2,%3}, [%4];"
        : "=r"(r0),"=r"(r1),"=r"(r2),"=r"(r3) : "r"(a));
}
__device__ __forceinline__ void ldm4t(unsigned& r0,unsigned& r1,unsigned& r2,unsigned& r3,unsigned a){
    asm volatile("ldmatrix.sync.aligned.m8n8.x4.trans.shared.b16 {%0,%1,%2,%3}, [%4];"
        : "=r"(r0),"=r"(r1),"=r"(r2),"=r"(r3) : "r"(a));
}
__device__ __forceinline__ void ldm2t(unsigned& r0,unsigned& r1,unsigned a){
    asm volatile("ldmatrix.sync.aligned.m8n8.x2.trans.shared.b16 {%0,%1}, [%2];"
        : "=r"(r0),"=r"(r1) : "r"(a));
}
__device__ __forceinline__ void mma_f16(float* c, unsigned a0,unsigned a1,unsigned a2,unsigned a3,
                                        unsigned b0, unsigned b1){
    asm volatile("mma.sync.aligned.m16n8k16.row.col.f32.f16.f16.f32 "
        "{%0,%1,%2,%3},{%4,%5,%6,%7},{%8,%9},{%0,%1,%2,%3};"
        : "+f"(c[0]),"+f"(c[1]),"+f"(c[2]),"+f"(c[3])
        : "r"(a0),"r"(a1),"r"(a2),"r"(a3),"r"(b0),"r"(b1));
}
__device__ __forceinline__ float ex2(float x){
    float r; asm("ex2.approx.f32 %0, %1;" : "=f"(r) : "f"(x)); return r;
}
__device__ __forceinline__ void st2(__half* p, float x, float y){
    *(__half2*)p = __floats2half2_rn(x, y);
}
__device__ __forceinline__ void st2(float* p, float x, float y){
    *(float2*)p = make_float2(x, y);
}

// ---------------- fp32 -> fp16 converts (merged launches, 8 elem/thread) ----
__global__ void f2h_acts(const float* __restrict__ q, const float* __restrict__ k,
                         const float* __restrict__ v){
    const float* s; __half* d;
    if      (blockIdx.z == 0){ s = q; d = h_query; }
    else if (blockIdx.z == 1){ s = k; d = h_key;   }
    else                     { s = v; d = h_value; }
    int i = (blockIdx.x*blockDim.x + threadIdx.x)*8;
    float4 a = *(const float4*)&s[i];
    float4 b2 = *(const float4*)&s[i+4];
    *(__half2*)&d[i]   = __floats2half2_rn(a.x, a.y);
    *(__half2*)&d[i+2] = __floats2half2_rn(a.z, a.w);
    *(__half2*)&d[i+4] = __floats2half2_rn(b2.x, b2.y);
    *(__half2*)&d[i+6] = __floats2half2_rn(b2.z, b2.w);
}
__global__ void f2h_wts(const float* __restrict__ Wq, const float* __restrict__ Wo,
                        const float* __restrict__ Wk, const float* __restrict__ Wv){
    const float* s; __half* d; int n; float sc;
    if      (blockIdx.z == 0){ s=Wq; d=h_Wq; n=DMODEL*DMODEL; sc=QSCALE; }
    else if (blockIdx.z == 1){ s=Wo; d=h_Wo; n=DMODEL*DMODEL; sc=1.f; }
    else if (blockIdx.z == 2){ s=Wk; d=h_Wk; n=DMODEL*DK;     sc=1.f; }
    else                     { s=Wv; d=h_Wv; n=DMODEL*DK;     sc=1.f; }
    int i = (blockIdx.x*blockDim.x + threadIdx.x)*8;
    if (i < n){
        float4 a = *(const float4*)&s[i];
        float4 b2 = *(const float4*)&s[i+4];
        *(__half2*)&d[i]   = __floats2half2_rn(a.x*sc, a.y*sc);
        *(__half2*)&d[i+2] = __floats2half2_rn(a.z*sc, a.w*sc);
        *(__half2*)&d[i+4] = __floats2half2_rn(b2.x*sc, b2.y*sc);
        *(__half2*)&d[i+6] = __floats2half2_rn(b2.z*sc, b2.w*sc);
    }
}

// ---------------------------------------------------------------------------
// fp16 GEMM core: C[M,N] = A[M,K] @ W[K,N] + bias*bscale.
// BM x BN tiles, BK=32. 256 threads, 8 warps arranged (BM/32 m) x (8/(BM/32) n).
// cp.async double-buffered, ldmatrix fragments, fp16 m16n8k16 mma, f32 accum.
// Output row stride CST (>= N) at column offset coff.
// ---------------------------------------------------------------------------
template<int BM, int BN, typename OUT>
__device__ __forceinline__ void gemm_core(
    const __half* __restrict__ A, const __half* __restrict__ W,
    const float* __restrict__ bias, OUT* __restrict__ C,
    int M, int N, int K, float bscale, int CST, int coff,
    __half* sAbase, __half* sWbase)
{
    constexpr int AST = 40;            // A smem row stride (halfs)
    constexpr int WST = BN + 8;        // W smem row stride
    constexpr int MW  = BM/32;         // warps in m
    constexpr int NW  = 8/MW;          // warps in n
    constexpr int WN  = BN/NW;         // warp n extent
    constexpr int NG  = WN/16;         // n16 groups per warp

    const int tid = threadIdx.x, warp = tid>>5, lane = tid&31;
    const int wm = warp % MW, wn = warp / MW;
    const int m0 = blockIdx.y*BM, n0 = blockIdx.x*BN;
    const int g = lane>>2, t = lane&3;

    float acc[2][NG*2][4];
#pragma unroll
    for (int a=0;a<2;a++)
#pragma unroll
        for (int b=0;b<NG*2;b++)
#pragma unroll
            for (int c=0;c<4;c++) acc[a][b][c]=0.f;

    auto stage = [&](int kt, int buf){
        __half* sA = sAbase + buf*(BM*AST);
        __half* sW = sWbase + buf*(32*WST);
#pragma unroll
        for (int c = tid; c < BM*4; c += 256){
            int r = c>>2, cc = c&3;
            cp16(su32(&sA[r*AST + cc*8]),
                 &A[(size_t)(m0+r)*K + kt*32 + cc*8]);
        }
        constexpr int WC = BN/8;
#pragma unroll
        for (int c2=tid; c2 < 32*WC; c2 += 256){
            int r = c2/WC, cc = c2%WC;
            cp16(su32(&sW[r*WST + cc*8]),
                 &W[(size_t)(kt*32+r)*N + n0 + cc*8]);
        }
    };

    const int KT = K/32;
    stage(0,0); cp_commit();

    for (int kt = 0; kt < KT; kt++){
        if (kt+1 < KT){ stage(kt+1, (kt+1)&1); cp_commit(); cp_wait<1>(); }
        else          { cp_wait<0>(); }
        __syncthreads();
        const __half* cA = sAbase + (kt&1)*(BM*AST);
        const __half* cW = sWbase + (kt&1)*(32*WST);
#pragma unroll
        for (int ks=0; ks<2; ks++){
            unsigned a[2][4];
#pragma unroll
            for (int mt=0; mt<2; mt++){
                int row = wm*32 + mt*16 + (lane&7) + ((lane>>3)&1)*8;
                int col = ks*16 + (lane>>4)*8;
                ldm4(a[mt][0],a[mt][1],a[mt][2],a[mt][3], su32(&cA[row*AST+col]));
            }
            unsigned bfr[NG][4];
#pragma unroll
            for (int ng=0; ng<NG; ng++){
                int row = ks*16 + (lane&15);
                int col = wn*WN + ng*16 + (lane>>4)*8;
                ldm4t(bfr[ng][0],bfr[ng][1],bfr[ng][2],bfr[ng][3], su32(&cW[row*WST+col]));
            }
#pragma unroll
            for (int mt=0; mt<2; mt++)
#pragma unroll
                for (int ng=0; ng<NG; ng++){
                    mma_f16(acc[mt][ng*2],   a[mt][0],a[mt][1],a[mt][2],a[mt][3],
                            bfr[ng][0],bfr[ng][1]);
                    mma_f16(acc[mt][ng*2+1], a[mt][0],a[mt][1],a[mt][2],a[mt][3],
                            bfr[ng][2],bfr[ng][3]);
                }
        }
        __syncthreads();
    }

#pragma unroll
    for (int mt=0; mt<2; mt++){
        int row = m0 + wm*32 + mt*16;
#pragma unroll
        for (int nt=0; nt<NG*2; nt++){
            int col = n0 + wn*WN + nt*8 + 2*t;
            float b0 = bias[col]*bscale, b1 = bias[col+1]*bscale;
            st2(&C[(size_t)(row+g  )*CST + coff + col], acc[mt][nt][0]+b0, acc[mt][nt][1]+b1);
            st2(&C[(size_t)(row+g+8)*CST + coff + col], acc[mt][nt][2]+b0, acc[mt][nt][3]+b1);
        }
    }
}

// BM=128, BN=128 instantiation (Q-proj / O-proj)
template<typename OUT>
__global__ __launch_bounds__(256,2) void gemm128_k(
    const __half* __restrict__ A, const __half* __restrict__ W,
    const float* __restrict__ bias, OUT* __restrict__ C,
    int M, int N, int K, float bscale)
{
    __shared__ __half sA[2*128*40];
    __shared__ __half sW[2*32*136];
    gemm_core<128,128,OUT>(A, W, bias, C, M, N, K, bscale, N, 0, sA, sW);
}

// BM=64, BN=64: K-proj and V-proj merged via blockIdx.z into packed h_kv.
// 128 CTAs total -> near-full chip for this bandwidth-bound projection.
__global__ __launch_bounds__(256,2) void gemm_kv_k(
    const __half* __restrict__ Ak, const __half* __restrict__ Av,
    const __half* __restrict__ Wk, const __half* __restrict__ Wv,
    const float* __restrict__ bk, const float* __restrict__ bv,
    __half* __restrict__ C)
{
    __shared__ __half sA[2*64*40];
    __shared__ __half sW[2*32*72];
    const int z = blockIdx.z;
    gemm_core<64,64,__half>(z ? Av : Ak, z ? Wv : Wk, z ? bv : bk, C,
                            ROWS, DK, DMODEL, 1.f, 2*DK, z*DK, sA, sW);
}

// ---------------------------------------------------------------------------
// fp16 flash attention, MQA flattened: rows (b,s,h), M=65536, N=2048, D=64.
// CTA = 128 rows = 8 s x 16 heads; warp = one s (16 head-rows).
// Q pre-scaled by 0.125*log2(e) -> softmax via exp2 (f16x2 MUFU).
// Softmax denominator l accumulated by the P*V mma via a ones-column in V.
// K|V packed in h_kv (row stride 128). cp.async double-buffered 64-key tiles.
// ---------------------------------------------------------------------------
__global__ __launch_bounds__(256,2) void flash_h(
    const __half* __restrict__ qp, const __half* __restrict__ kvp,
    const int* __restrict__ mask, __half* __restrict__ xo)
{
    constexpr int ST = 72;    // smem row stride halfs; cols 64-71 = [1,0,...,0]
    __shared__ __half sK[2][64*ST];
    __shared__ __half sV[2][64*ST];
    __shared__ int    sM[2][8*64];
    __half* sQ = &sK[0][0];   // 128*72 halfs == both sK buffers, reused in prologue

    const int tid = threadIdx.x, warp = tid>>5, lane = tid&31;
    const int g = lane>>2, t = lane&3;
    const int m0 = blockIdx.x*128;
    const int b  = m0 >> 15;
    const int s0 = (m0 & 32767) >> 4;
    const int sbase = b*SEQ;

    // ---- stage Q [128][64] via cp.async, extract A-fragments ----
    {
        int c = tid*4;
#pragma unroll
        for (int i=0;i<4;i++,c++){
            int r = c>>3, cc = c&7;
            cp16(su32(&sQ[r*ST + cc*8]),
                 &qp[(size_t)(sbase + s0 + (r>>4))*DMODEL + (r&15)*64 + cc*8]);
        }
        cp_commit(); cp_wait<0>();
        __syncthreads();
    }
    unsigned qa[4][4];
#pragma unroll
    for (int ks=0; ks<4; ks++){
        int row = warp*16 + (lane&7) + ((lane>>3)&1)*8;
        int col = ks*16 + (lane>>4)*8;
        ldm4(qa[ks][0],qa[ks][1],qa[ks][2],qa[ks][3], su32(&sQ[row*ST+col]));
    }
    __syncthreads();    // sQ region free -> K buffers

    // ---- init V ones-column region (cols 64-71) for both buffers ----
    if (tid < 128){
        int buf = tid >> 6, row = tid & 63;
        __half tmp[8] = {__float2half(1.f),__half(0),__half(0),__half(0),
                         __half(0),__half(0),__half(0),__half(0)};
        *(uint4*)&sV[buf][row*ST + 64] = *(uint4*)&tmp[0];
    }

    float o[8][4];
#pragma unroll
    for (int i=0;i<8;i++){ o[i][0]=0.f;o[i][1]=0.f;o[i][2]=0.f;o[i][3]=0.f; }
    float lacc[4] = {0.f,0.f,0.f,0.f};
    float mrow0=-1e30f, mrow1=-1e30f;

    auto stage = [&](int nk, int buf){
        int c = tid*2;
#pragma unroll
        for (int i=0;i<2;i++,c++){
            int r = c>>3, cc = c&7;
            const __half* kvrow = &kvp[(size_t)(sbase + nk + r)*(2*DK)];
            cp16(su32(&sK[buf][r*ST + cc*8]), kvrow + cc*8);
            cp16(su32(&sV[buf][r*ST + cc*8]), kvrow + DK + cc*8);
        }
        if (tid < 128){
            int r = tid>>4, cc = tid&15;
            cp16(su32(&sM[buf][r*64 + cc*4]),
                 &mask[((size_t)b*SEQ + s0 + r)*SEQ + nk + cc*4]);
        }
    };

    stage(0,0); cp_commit();

    for (int it = 0; it < SEQ/64; it++){
        if (it+1 < SEQ/64){ stage((it+1)*64, (it+1)&1); cp_commit(); cp_wait<1>(); }
        else              { cp_wait<0>(); }
        __syncthreads();
        const __half* cK = sK[it&1];
        const __half* cV = sV[it&1];
        const int*    cM = sM[it&1];

        // ---- S = Q K^T + mask (log2 domain) ----
        float sf[8][4];
#pragma unroll
        for (int jt=0; jt<8; jt++){
            unsigned kb[8];
            {
                int row = jt*8 + (lane&7);
                int col = (lane>>3)*8;
                ldm4(kb[0],kb[1],kb[2],kb[3], su32(&cK[row*ST + col]));
                ldm4(kb[4],kb[5],kb[6],kb[7], su32(&cK[row*ST + 32 + col]));
            }
            sf[jt][0]=0.f; sf[jt][1]=0.f; sf[jt][2]=0.f; sf[jt][3]=0.f;
            mma_f16(sf[jt], qa[0][0],qa[0][1],qa[0][2],qa[0][3], kb[0],kb[1]);
            mma_f16(sf[jt], qa[1][0],qa[1][1],qa[1][2],qa[1][3], kb[2],kb[3]);
            mma_f16(sf[jt], qa[2][0],qa[2][1],qa[2][2],qa[2][3], kb[4],kb[5]);
            mma_f16(sf[jt], qa[3][0],qa[3][1],qa[3][2],qa[3][3], kb[6],kb[7]);
            float mb0 = cM[warp*64 + jt*8 + 2*t    ] ? 0.f : -1e9f;
            float mb1 = cM[warp*64 + jt*8 + 2*t + 1] ? 0.f : -1e9f;
            sf[jt][0]+=mb0; sf[jt][1]+=mb1; sf[jt][2]+=mb0; sf[jt][3]+=mb1;
        }

        // ---- online softmax (base 2), P in f16 via h2exp2 ----
        float mx0=-1e30f, mx1=-1e30f;
#pragma unroll
        for (int jt=0; jt<8; jt++){
            mx0 = fmaxf(mx0, fmaxf(sf[jt][0], sf[jt][1]));
            mx1 = fmaxf(mx1, fmaxf(sf[jt][2], sf[jt][3]));
        }
        mx0 = fmaxf(mx0, __shfl_xor_sync(0xffffffffu, mx0, 1));
        mx0 = fmaxf(mx0, __shfl_xor_sync(0xffffffffu, mx0, 2));
        mx1 = fmaxf(mx1, __shfl_xor_sync(0xffffffffu, mx1, 1));
        mx1 = fmaxf(mx1, __shfl_xor_sync(0xffffffffu, mx1, 2));

        float mn0 = fmaxf(mrow0, mx0), mn1 = fmaxf(mrow1, mx1);
        float sc0 = ex2(mrow0 - mn0), sc1 = ex2(mrow1 - mn1);
        mrow0 = mn0; mrow1 = mn1;

        unsigned pl[8], ph[8];
#pragma unroll
        for (int jt=0; jt<8; jt++){
            __half2 e0 = h2exp2(__floats2half2_rn(sf[jt][0]-mn0, sf[jt][1]-mn0));
            __half2 e1 = h2exp2(__floats2half2_rn(sf[jt][2]-mn1, sf[jt][3]-mn1));
            pl[jt] = *(unsigned*)&e0;
            ph[jt] = *(unsigned*)&e1;
        }

#pragma unroll
        for (int nv=0; nv<8; nv++){
            o[nv][0]*=sc0; o[nv][1]*=sc0; o[nv][2]*=sc1; o[nv][3]*=sc1;
        }
        lacc[0]*=sc0; lacc[1]*=sc0; lacc[2]*=sc1; lacc[3]*=sc1;

        // ---- O += P V ; l += P 1 (ones-column mma) ----
#pragma unroll
        for (int kt2=0; kt2<4; kt2++){
            unsigned a0 = pl[2*kt2],   a1 = ph[2*kt2];
            unsigned a2 = pl[2*kt2+1], a3 = ph[2*kt2+1];
#pragma unroll
            for (int dp=0; dp<4; dp++){
                unsigned r0,r1,r2,r3;
                int row = kt2*16 + (lane&15);
                int col = dp*16 + (lane>>4)*8;
                ldm4t(r0,r1,r2,r3, su32(&cV[row*ST + col]));
                mma_f16(o[dp*2],   a0,a1,a2,a3, r0,r1);
                mma_f16(o[dp*2+1], a0,a1,a2,a3, r2,r3);
            }
            unsigned l0r,l1r;
            ldm2t(l0r,l1r, su32(&cV[(kt2*16 + (lane&15))*ST + 64]));
            mma_f16(lacc, a0,a1,a2,a3, l0r,l1r);
        }
        __syncthreads();
    }

    // ---- broadcast l (col 64 lives in t=0 lanes, reg 0/2), normalize, write ----
    float lv0 = __shfl_sync(0xffffffffu, lacc[0], lane & 28);
    float lv1 = __shfl_sync(0xffffffffu, lacc[2], lane & 28);
    float inv0 = 1.f/lv0, inv1 = 1.f/lv1;
    __half* orow = &xo[(size_t)(sbase + s0 + warp)*DMODEL];
#pragma unroll
    for (int nt=0; nt<8; nt++){
        int col = nt*8 + 2*t;
        st2(&orow[g*64 + col],     o[nt][0]*inv0, o[nt][1]*inv0);
        st2(&orow[(g+8)*64 + col], o[nt][2]*inv1, o[nt][3]*inv1);
    }
}

// ---------------------------------------------------------------------------
extern "C" void kernel_launch(void* const* d_in, const int* in_sizes, int n_in,
                              void* d_out, int out_size)
{
    const float* query = (const float*)d_in[0];
    const float* key   = (const float*)d_in[1];
    const float* value = (const float*)d_in[2];
    const int*   mask  = (const int*)  d_in[3];
    const float* Wq = (const float*)d_in[4];
    const float* bq = (const float*)d_in[5];
    const float* Wk = (const float*)d_in[6];
    const float* bk = (const float*)d_in[7];
    const float* Wv = (const float*)d_in[8];
    const float* bv = (const float*)d_in[9];
    const float* Wo = (const float*)d_in[10];
    const float* bo = (const float*)d_in[11];
    float* out = (float*)d_out;

    __half *gquery,*gkey,*gvalue,*gWq,*gWo,*gWk,*gWv,*gq,*gkv,*gx;
    cudaGetSymbolAddress((void**)&gquery, h_query);
    cudaGetSymbolAddress((void**)&gkey,   h_key);
    cudaGetSymbolAddress((void**)&gvalue, h_value);
    cudaGetSymbolAddress((void**)&gWq,    h_Wq);
    cudaGetSymbolAddress((void**)&gWo,    h_Wo);
    cudaGetSymbolAddress((void**)&gWk,    h_Wk);
    cudaGetSymbolAddress((void**)&gWv,    h_Wv);
    cudaGetSymbolAddress((void**)&gq,     h_q);
    cudaGetSymbolAddress((void**)&gkv,    h_kv);
    cudaGetSymbolAddress((void**)&gx,     h_x);

    const int NACT = ROWS*DMODEL;     // 4M
    const int NW   = DMODEL*DMODEL;   // 1M

    // converts: one launch for activations, one for all weights
    f2h_acts<<<dim3(NACT/2048, 1, 3), 256>>>(query, key, value);
    f2h_wts <<<dim3(NW/2048,   1, 4), 256>>>(Wq, Wo, Wk, Wv);

    // projections (Q; K & V merged at BM=64 -> 128 CTAs)
    gemm128_k<__half><<<dim3(DMODEL/128, ROWS/128), 256>>>(
        gquery, gWq, bq, gq, ROWS, DMODEL, DMODEL, QSCALE);
    gemm_kv_k<<<dim3(1, ROWS/64, 2), 256>>>(
        gkey, gvalue, gWk, gWv, bk, bv, gkv);

    // fused MQA flash attention
    flash_h<<<(NB*SEQ*NH)/128, 256>>>(gq, gkv, mask, gx);

    // output projection (fp32 out)
    gemm128_k<float><<<dim3(DMODEL/128, ROWS/128), 256>>>(
        gx, gWo, bo, out, ROWS, DMODEL, DMODEL, 1.f);
}